// round 4
// baseline (speedup 1.0000x reference)
#include <cuda_runtime.h>
#include <cuda_fp16.h>
#include <cstdint>

// ---------------------------------------------------------------- constants
#define NPTS    16384
#define KCODES  8192
#define DDIM    128
#define HWSZ    1024
#define MTILE   128              // points per CTA
#define CTILE   256              // codes per CTA code-tile
#define NCTILES (KCODES / CTILE) // 32
#define NCHUNK  6                // k-chunks of 64 (extended K = 384)
#define NSTAGES (NCTILES * NCHUNK)
#define ZSTRIDE 392              // halves per zs row -> conflict-free ldmatrix
#define BSTRIDE 72               // halves per B row  -> conflict-free ldmatrix
#define BUFB    (CTILE * BSTRIDE * 2)  // 36864 bytes per B buffer
#define NBUF    3

// Output layout (concatenated float32 outputs)
#define O_ZQ  0
#define O_IDX 2097152
#define O_CB  2113536
#define O_CNT 3162112
#define O_WT  3170304

// ---------------------------------------------------------------- scratch
__device__ float  g_cnorm[KCODES];
__device__ __half g_bext[6u * KCODES * 64];   // [chunk][code][64] fp16
__device__ int    g_idx[NPTS];
__device__ float  g_counts[KCODES];
__device__ float  g_dw[KCODES * DDIM];

// ---------------------------------------------------------------- helpers
__device__ __forceinline__ uint32_t smem_u32(const void* p) {
    uint32_t a;
    asm("{ .reg .u64 t; cvta.to.shared.u64 t, %1; cvt.u32.u64 %0, t; }" : "=r"(a) : "l"(p));
    return a;
}
__device__ __forceinline__ void cp_async16(uint32_t dst, const void* src) {
    asm volatile("cp.async.cg.shared.global [%0], [%1], 16;" :: "r"(dst), "l"(src) : "memory");
}
#define CP_COMMIT() asm volatile("cp.async.commit_group;" ::: "memory")
#define CP_WAIT1()  asm volatile("cp.async.wait_group 1;" ::: "memory")
#define CP_WAIT0()  asm volatile("cp.async.wait_group 0;" ::: "memory")

#define LDSM4(r0, r1, r2, r3, a)                                              \
    asm volatile("ldmatrix.sync.aligned.m8n8.x4.shared.b16 {%0,%1,%2,%3}, [%4];" \
                 : "=r"(r0), "=r"(r1), "=r"(r2), "=r"(r3) : "r"(a))

#define MMA16816(c, a0, a1, a2, a3, b0, b1)                                  \
    asm volatile("mma.sync.aligned.m16n8k16.row.col.f32.f16.f16.f32 "        \
                 "{%0,%1,%2,%3}, {%4,%5,%6,%7}, {%8,%9}, {%0,%1,%2,%3};"     \
                 : "+f"((c)[0]), "+f"((c)[1]), "+f"((c)[2]), "+f"((c)[3])    \
                 : "r"(a0), "r"(a1), "r"(a2), "r"(a3), "r"(b0), "r"(b1))

// ---------------------------------------------------------------- prep kernels
__global__ void prep_kernel(const float* __restrict__ cb) {
    int k = blockIdx.x, t = threadIdx.x;
    float v = cb[k * DDIM + t];
    g_dw[k * DDIM + t] = 0.0f;
    float sq = v * v;
    #pragma unroll
    for (int o = 16; o > 0; o >>= 1) sq += __shfl_down_sync(0xffffffffu, sq, o);
    __shared__ float red[4];
    if ((t & 31) == 0) red[t >> 5] = sq;
    __syncthreads();
    if (t == 0) { g_cnorm[k] = red[0] + red[1] + red[2] + red[3]; g_counts[k] = 0.0f; }
}

// fp16 hi/lo split of the codebook into [chunk][code][64] rows (128B each)
__global__ void bext_kernel(const float* __restrict__ cb) {
    int i = blockIdx.x * blockDim.x + threadIdx.x;
    int k = i >> 7, d = i & 127;
    float c = cb[i];
    __half h = __float2half_rn(c);
    __half l = __float2half_rn(c - __half2float(h));
    int half_ = d >> 6, pos = d & 63;
    size_t ro = (size_t)k * 64 + pos;
    const size_t BS = (size_t)KCODES * 64;
    g_bext[(size_t)half_ * BS + ro] = h;   // chunks 0,1: c_hi
    g_bext[(2 + half_) * BS + ro]   = l;   // chunks 2,3: c_lo
    g_bext[(4 + half_) * BS + ro]   = h;   // chunks 4,5: c_hi
}

// ---------------------------------------------------------------- argmin (HMMA)
// grid = 128 CTAs, block = 256 (8 warps: 2 in M x 4 in N), warp tile 64x64.
__global__ void __launch_bounds__(256, 1) argmin_kernel(const float* __restrict__ z,
                                                        float* __restrict__ out) {
    extern __shared__ char smem[];
    __half* zs = (__half*)smem;                                   // 128*392*2 = 100352 B
    char*   bbase = smem + MTILE * ZSTRIDE * 2;                   // 3 x 36864 B

    const int tid = threadIdx.x;
    const int lane = tid & 31, wid = tid >> 5;
    const int wm = wid & 1;        // m block (64 rows)
    const int wn = wid >> 1;       // n block (64 cols)

    // ---- stage z tile: build fp16 hi/hi/lo extended rows (one-time)
    const int pbase = blockIdx.x * MTILE;
    const int b = pbase >> 10, hw0 = pbase & (HWSZ - 1);
    const float* zb = z + (size_t)b * DDIM * HWSZ + hw0;
    for (int i = tid; i < DDIM * MTILE; i += 256) {
        int d = i >> 7, p = i & 127;
        float v = zb[(size_t)d * HWSZ + p];
        __half h = __float2half_rn(v);
        __half l = __float2half_rn(v - __half2float(h));
        zs[p * ZSTRIDE + d]       = h;   // chunks 0,1 pair with c_hi
        zs[p * ZSTRIDE + 128 + d] = h;   // chunks 2,3 pair with c_lo
        zs[p * ZSTRIDE + 256 + d] = l;   // chunks 4,5 pair with c_hi
    }

    const uint32_t bb32 = smem_u32(bbase);
    const uint32_t zs32 = smem_u32(zs);

    // ldmatrix base addresses (lane-dependent): row = lane&15, koff = (lane>>4)*8
    const uint32_t za0 = zs32 + 2u * ((wm * 64 + (lane & 15)) * ZSTRIDE + (lane >> 4) * 8);
    const uint32_t bb0 = 2u * ((wn * 64 + (lane & 15)) * BSTRIDE + (lane >> 4) * 8);

    // ---- producer: one 256x64-half B chunk per stage via cp.async
    auto issue = [&](int s) {
        int ct = s / NCHUNK, c = s - ct * NCHUNK;
        const char* src = (const char*)(g_bext + ((size_t)c * KCODES + (size_t)ct * CTILE) * 64);
        uint32_t dst = bb32 + (uint32_t)(s % NBUF) * BUFB;
        #pragma unroll
        for (int i = 0; i < 8; i++) {
            int idx = tid + i * 256;                 // 0..2047 16B chunks
            cp_async16(dst + (uint32_t)(idx >> 3) * 144u + (uint32_t)(idx & 7) * 16u,
                       src + (size_t)idx * 16);
        }
        CP_COMMIT();
    };

    float acc[4][8][4];
    float minv[8];
    int   mini[8];
    #pragma unroll
    for (int s = 0; s < 8; s++) { minv[s] = 3.402823466e38f; mini[s] = 0; }

    issue(0);
    issue(1);

    for (int s = 0; s < NSTAGES; s++) {
        const int ct = s / NCHUNK, c = s - ct * NCHUNK;
        if (s + 1 < NSTAGES) CP_WAIT1(); else CP_WAIT0();
        __syncthreads();                       // buf s visible; frees buf (s+2)%3
        if (s + 2 < NSTAGES) issue(s + 2);

        if (c == 0) {
            #pragma unroll
            for (int mt = 0; mt < 4; mt++)
                #pragma unroll
                for (int nt = 0; nt < 8; nt++)
                    #pragma unroll
                    for (int r = 0; r < 4; r++) acc[mt][nt][r] = 0.0f;
        }

        const uint32_t za = za0 + (uint32_t)c * 128u;                  // c*64 halves
        const uint32_t bbuf = bb32 + (uint32_t)(s % NBUF) * BUFB + bb0;

        #pragma unroll
        for (int ks = 0; ks < 4; ks++) {
            uint32_t a[4][4];
            #pragma unroll
            for (int mt = 0; mt < 4; mt++)
                LDSM4(a[mt][0], a[mt][1], a[mt][2], a[mt][3],
                      za + (uint32_t)mt * (16u * ZSTRIDE * 2u) + (uint32_t)ks * 32u);
            uint32_t bf[4][4];
            #pragma unroll
            for (int np = 0; np < 4; np++)
                LDSM4(bf[np][0], bf[np][1], bf[np][2], bf[np][3],
                      bbuf + (uint32_t)np * (16u * BSTRIDE * 2u) + (uint32_t)ks * 32u);
            #pragma unroll
            for (int np = 0; np < 4; np++) {
                #pragma unroll
                for (int mt = 0; mt < 4; mt++)
                    MMA16816(acc[mt][2 * np], a[mt][0], a[mt][1], a[mt][2], a[mt][3],
                             bf[np][0], bf[np][2]);
                #pragma unroll
                for (int mt = 0; mt < 4; mt++)
                    MMA16816(acc[mt][2 * np + 1], a[mt][0], a[mt][1], a[mt][2], a[mt][3],
                             bf[np][1], bf[np][3]);
            }
        }

        if (c == NCHUNK - 1) {
            // epilogue: dist = cnorm - 2*dot; running first-argmin in registers.
            const int code0 = ct * CTILE + wn * 64 + (lane & 3) * 2;
            #pragma unroll
            for (int nt = 0; nt < 8; nt++) {
                const int kk = code0 + nt * 8;
                const float2 cn = __ldg(reinterpret_cast<const float2*>(g_cnorm + kk));
                #pragma unroll
                for (int mt = 0; mt < 4; mt++) {
                    const int s0 = mt * 2;
                    float d0 = fmaf(-2.0f, acc[mt][nt][0], cn.x);
                    float d1 = fmaf(-2.0f, acc[mt][nt][1], cn.y);
                    if (d0 < minv[s0]) { minv[s0] = d0; mini[s0] = kk; }
                    if (d1 < minv[s0]) { minv[s0] = d1; mini[s0] = kk + 1; }
                    float d2 = fmaf(-2.0f, acc[mt][nt][2], cn.x);
                    float d3 = fmaf(-2.0f, acc[mt][nt][3], cn.y);
                    if (d2 < minv[s0 + 1]) { minv[s0 + 1] = d2; mini[s0 + 1] = kk; }
                    if (d3 < minv[s0 + 1]) { minv[s0 + 1] = d3; mini[s0 + 1] = kk + 1; }
                }
            }
        }
    }

    // ---- final reduce. Quad shuffle, then across wn via SMEM (reuse zs).
    __syncthreads();
    float* rv = (float*)smem;
    int*   ri = (int*)smem + 512;
    #pragma unroll
    for (int s2 = 0; s2 < 8; s2++) {
        float v = minv[s2];
        int   i = mini[s2];
        #pragma unroll
        for (int off = 1; off <= 2; off <<= 1) {
            float ov = __shfl_xor_sync(0xffffffffu, v, off);
            int   oi = __shfl_xor_sync(0xffffffffu, i, off);
            if (ov < v || (ov == v && oi < i)) { v = ov; i = oi; }
        }
        if ((lane & 3) == 0) {
            int row = wm * 64 + (s2 >> 1) * 16 + (s2 & 1) * 8 + (lane >> 2);
            rv[row * 4 + wn] = v;
            ri[row * 4 + wn] = i;
        }
    }
    __syncthreads();
    if (tid < MTILE) {
        float bv = rv[tid * 4];
        int   bi = ri[tid * 4];
        #pragma unroll
        for (int t = 1; t < 4; t++) {
            float v = rv[tid * 4 + t];
            int  ii = ri[tid * 4 + t];
            if (v < bv || (v == bv && ii < bi)) { bv = v; bi = ii; }
        }
        g_idx[pbase + tid] = bi;
        out[O_IDX + pbase + tid] = (float)bi;   // fused indices output
    }
}

// ---------------------------------------------------------------- downstream
__global__ void accum_kernel(const float* __restrict__ z) {
    int n = blockIdx.x, d = threadIdx.x;
    int idx = g_idx[n];
    int b = n >> 10, hw = n & (HWSZ - 1);
    float zv = z[((size_t)b * DDIM + d) * HWSZ + hw];
    atomicAdd(&g_dw[idx * DDIM + d], zv);
    if (d == 0) atomicAdd(&g_counts[idx], 1.0f);
}

__global__ void finalize_kernel(const float* __restrict__ ema_count,
                                const float* __restrict__ ema_weight,
                                float* __restrict__ out) {
    int k = blockIdx.x, d = threadIdx.x;
    float cnt = ema_count[k] * 0.99f + 0.01f * g_counts[k];
    float w = ema_weight[(size_t)k * DDIM + d] * 0.99f + 0.01f * g_dw[(size_t)k * DDIM + d];
    out[O_WT + (size_t)k * DDIM + d] = w;
    out[O_CB + (size_t)k * DDIM + d] = w / fmaxf(cnt, 1.0f);
    if (d == 0) out[O_CNT + k] = cnt;
}

// z_q straight-through: stage gathered codebook rows via SMEM so both the
// codebook reads and the (B,D,H,W) writes are coalesced.
__global__ void zq_kernel(const float* __restrict__ z,
                          const float* __restrict__ cb,
                          float* __restrict__ out) {
    __shared__ float q[32 * 129];
    const int n0 = blockIdx.x * 32;
    const int b = n0 >> 10, hw0 = n0 & (HWSZ - 1);
    for (int j = threadIdx.x; j < 32 * 128; j += 256) {
        int p = j >> 7, d = j & 127;
        q[p * 129 + d] = cb[(size_t)g_idx[n0 + p] * DDIM + d];
    }
    __syncthreads();
    const float* zp = z + (size_t)b * DDIM * HWSZ + hw0;
    float* op = out + O_ZQ + (size_t)b * DDIM * HWSZ + hw0;
    for (int j = threadIdx.x; j < 32 * 128; j += 256) {
        int d = j >> 5, p = j & 31;
        float ze = zp[(size_t)d * HWSZ + p];
        float zq = q[p * 129 + d];
        op[(size_t)d * HWSZ + p] = ze + (zq - ze);
    }
}

// ---------------------------------------------------------------- launch
extern "C" void kernel_launch(void* const* d_in, const int* in_sizes, int n_in,
                              void* d_out, int out_size) {
    const float* z_e        = (const float*)d_in[0];
    const float* codebook   = (const float*)d_in[1];
    const float* ema_count  = (const float*)d_in[2];
    const float* ema_weight = (const float*)d_in[3];
    float* out = (float*)d_out;

    const int SMEM_DYN = MTILE * ZSTRIDE * 2 + NBUF * BUFB;  // 100352 + 110592 = 210944
    static int smem_set = 0;
    if (!smem_set) {
        cudaFuncSetAttribute(argmin_kernel, cudaFuncAttributeMaxDynamicSharedMemorySize, SMEM_DYN);
        smem_set = 1;
    }

    prep_kernel<<<KCODES, 128>>>(codebook);
    bext_kernel<<<(KCODES * DDIM) / 256, 256>>>(codebook);
    argmin_kernel<<<NPTS / MTILE, 256, SMEM_DYN>>>(z_e, out);
    accum_kernel<<<NPTS, 128>>>(z_e);
    finalize_kernel<<<KCODES, 128>>>(ema_count, ema_weight, out);
    zq_kernel<<<NPTS / 32, 256>>>(z_e, codebook, out);
}

// round 5
// speedup vs baseline: 1.0808x; 1.0808x over previous
#include <cuda_runtime.h>
#include <cuda_fp16.h>
#include <cstdint>

// ---------------------------------------------------------------- constants
#define NPTS    16384
#define KCODES  8192
#define DDIM    128
#define HWSZ    1024
#define MTILE   128                 // points per item
#define CTILE   256                 // codes per MMA code-tile
#define NSPLIT  8                   // K-splits (1024 codes each)
#define KPER    (KCODES / NSPLIT)   // 1024
#define NCT     (KPER / CTILE)      // 4 code-tiles per item
#define NCHUNK  6                   // 64-half k-chunks (ext K = 384)
#define NSTAGES (NCT * NCHUNK)      // 24 stages per item
#define NITEMS  (NSPLIT * (NPTS / MTILE))  // 1024
#define ZSTRIDE 392                 // halves per zs row (conflict-free ldmatrix)
#define BSTRIDE 72                  // halves per B row
#define BUFB    (CTILE * BSTRIDE * 2)     // 36864 B
#define NBUF    3

// Output layout (concatenated float32 outputs)
#define O_ZQ  0
#define O_IDX 2097152
#define O_CB  2113536
#define O_CNT 3162112
#define O_WT  3170304

// ---------------------------------------------------------------- scratch
__device__ float  g_cnorm[KCODES];
__device__ __half g_bext[6u * KCODES * 64];       // [chunk][code][64]
__device__ __half g_zext[(NPTS / MTILE) * MTILE * 384];  // [tile][p][384], 12MB
__device__ int    g_idx[NPTS];
__device__ float  g_counts[KCODES];
__device__ float  g_dw[KCODES * DDIM];
__device__ float  g_pv[NSPLIT * NPTS];
__device__ int    g_pi[NSPLIT * NPTS];

// ---------------------------------------------------------------- helpers
__device__ __forceinline__ uint32_t smem_u32(const void* p) {
    uint32_t a;
    asm("{ .reg .u64 t; cvta.to.shared.u64 t, %1; cvt.u32.u64 %0, t; }" : "=r"(a) : "l"(p));
    return a;
}
__device__ __forceinline__ void cp_async16(uint32_t dst, const void* src) {
    asm volatile("cp.async.cg.shared.global [%0], [%1], 16;" :: "r"(dst), "l"(src) : "memory");
}
#define CP_COMMIT() asm volatile("cp.async.commit_group;" ::: "memory")
#define CP_WAIT1()  asm volatile("cp.async.wait_group 1;" ::: "memory")
#define CP_WAIT0()  asm volatile("cp.async.wait_group 0;" ::: "memory")

#define LDSM4(r0, r1, r2, r3, a)                                              \
    asm volatile("ldmatrix.sync.aligned.m8n8.x4.shared.b16 {%0,%1,%2,%3}, [%4];" \
                 : "=r"(r0), "=r"(r1), "=r"(r2), "=r"(r3) : "r"(a))

#define MMA16816(c, a0, a1, a2, a3, b0, b1)                                  \
    asm volatile("mma.sync.aligned.m16n8k16.row.col.f32.f16.f16.f32 "        \
                 "{%0,%1,%2,%3}, {%4,%5,%6,%7}, {%8,%9}, {%0,%1,%2,%3};"     \
                 : "+f"((c)[0]), "+f"((c)[1]), "+f"((c)[2]), "+f"((c)[3])    \
                 : "r"(a0), "r"(a1), "r"(a2), "r"(a3), "r"(b0), "r"(b1))

// ---------------------------------------------------------------- prep: codebook side
// cnorm + zero accumulators + fp16 hi/lo split. grid=K, block=128
__global__ void prep_cb_kernel(const float* __restrict__ cb) {
    int k = blockIdx.x, t = threadIdx.x;
    float v = cb[k * DDIM + t];
    g_dw[k * DDIM + t] = 0.0f;

    __half h = __float2half_rn(v);
    __half l = __float2half_rn(v - __half2float(h));
    int half_ = t >> 6, pos = t & 63;
    size_t ro = (size_t)k * 64 + pos;
    const size_t BS = (size_t)KCODES * 64;
    g_bext[(size_t)half_ * BS + ro] = h;   // chunks 0,1: c_hi
    g_bext[(2 + half_) * BS + ro]   = l;   // chunks 2,3: c_lo
    g_bext[(4 + half_) * BS + ro]   = h;   // chunks 4,5: c_hi

    float sq = v * v;
    #pragma unroll
    for (int o = 16; o > 0; o >>= 1) sq += __shfl_down_sync(0xffffffffu, sq, o);
    __shared__ float red[4];
    if ((t & 31) == 0) red[t >> 5] = sq;
    __syncthreads();
    if (t == 0) { g_cnorm[k] = red[0] + red[1] + red[2] + red[3]; g_counts[k] = 0.0f; }
}

// ---------------------------------------------------------------- prep: z side
// build z_ext rows [p][hi(128) hi(128) lo(128)] per 128-point tile. grid=128, block=256
__global__ void prep_z_kernel(const float* __restrict__ z) {
    __shared__ float zsm[MTILE * 129];
    const int tile = blockIdx.x, tid = threadIdx.x;
    const int pbase = tile * MTILE;
    const int b = pbase >> 10, hw0 = pbase & (HWSZ - 1);
    const float* zb = z + (size_t)b * DDIM * HWSZ + hw0;
    for (int i = tid; i < DDIM * MTILE; i += 256) {
        int d = i >> 7, p = i & 127;
        zsm[p * 129 + d] = zb[(size_t)d * HWSZ + p];
    }
    __syncthreads();
    uint32_t* outp = reinterpret_cast<uint32_t*>(g_zext + (size_t)tile * MTILE * 384);
    for (int i = tid; i < MTILE * 192; i += 256) {
        int p = i / 192, c = i - p * 192;
        int q0 = 2 * c;
        int dd = q0 & 127;
        float v0 = zsm[p * 129 + dd];
        float v1 = zsm[p * 129 + dd + 1];
        __half h0, h1;
        if (q0 < 256) { h0 = __float2half_rn(v0); h1 = __float2half_rn(v1); }
        else {
            __half t0 = __float2half_rn(v0); h0 = __float2half_rn(v0 - __half2float(t0));
            __half t1 = __float2half_rn(v1); h1 = __float2half_rn(v1 - __half2float(t1));
        }
        __half2 hh = __halves2half2(h0, h1);
        outp[p * 192 + c] = *reinterpret_cast<uint32_t*>(&hh);
    }
}

// ---------------------------------------------------------------- argmin (HMMA)
// grid = 1024 items (ksplit-major), block = 256 (8 warps: 2M x 4N), warp tile 64x64.
__global__ void __launch_bounds__(256, 1) argmin_kernel() {
    extern __shared__ char smem[];
    char* bbase = smem + MTILE * ZSTRIDE * 2;                     // after zs

    const int tid = threadIdx.x;
    const int lane = tid & 31, wid = tid >> 5;
    const int wm = wid & 1;
    const int wn = wid >> 1;

    const int item = blockIdx.x;
    const int ksplit = item >> 7;          // 0..7
    const int tile = item & 127;           // 0..127
    const int kbeg = ksplit * KPER;
    const int pbase = tile * MTILE;

    const uint32_t zs32 = smem_u32(smem);
    const uint32_t bb32 = smem_u32(bbase);

    // ---- z tile: cp.async from precomputed g_zext into padded rows (group 0)
    {
        const char* zsrc = (const char*)(g_zext + (size_t)tile * MTILE * 384);
        for (int j = tid; j < 6144; j += 256) {
            int row = j / 48, c16 = j - row * 48;
            cp_async16(zs32 + (uint32_t)row * 784u + (uint32_t)c16 * 16u,
                       zsrc + (size_t)row * 768 + (size_t)c16 * 16);
        }
        CP_COMMIT();
    }

    // ldmatrix base addresses
    const uint32_t za0 = zs32 + 2u * ((wm * 64 + (lane & 15)) * ZSTRIDE + (lane >> 4) * 8);
    const uint32_t bb0 = 2u * ((wn * 64 + (lane & 15)) * BSTRIDE + (lane >> 4) * 8);

    // ---- producer: one 256x64-half B chunk per stage
    auto issue = [&](int s) {
        int ct = s / NCHUNK, c = s - ct * NCHUNK;
        const char* src = (const char*)(g_bext +
            ((size_t)c * KCODES + (size_t)(kbeg + ct * CTILE)) * 64);
        uint32_t dst = bb32 + (uint32_t)(s % NBUF) * BUFB;
        #pragma unroll
        for (int i = 0; i < 8; i++) {
            int idx = tid + i * 256;
            cp_async16(dst + (uint32_t)(idx >> 3) * 144u + (uint32_t)(idx & 7) * 16u,
                       src + (size_t)idx * 16);
        }
        CP_COMMIT();
    };

    float acc[4][8][4];
    float minv[8];
    int   mini[8];
    #pragma unroll
    for (int s = 0; s < 8; s++) { minv[s] = 3.402823466e38f; mini[s] = 0; }

    issue(0);
    issue(1);

    for (int s = 0; s < NSTAGES; s++) {
        const int ct = s / NCHUNK, c = s - ct * NCHUNK;
        if (s + 1 < NSTAGES) CP_WAIT1(); else CP_WAIT0();
        __syncthreads();
        if (s + 2 < NSTAGES) issue(s + 2);

        if (c == 0) {
            #pragma unroll
            for (int mt = 0; mt < 4; mt++)
                #pragma unroll
                for (int nt = 0; nt < 8; nt++)
                    #pragma unroll
                    for (int r = 0; r < 4; r++) acc[mt][nt][r] = 0.0f;
        }

        const uint32_t za = za0 + (uint32_t)c * 128u;
        const uint32_t bbuf = bb32 + (uint32_t)(s % NBUF) * BUFB + bb0;

        #pragma unroll
        for (int ks = 0; ks < 4; ks++) {
            uint32_t a[4][4];
            #pragma unroll
            for (int mt = 0; mt < 4; mt++)
                LDSM4(a[mt][0], a[mt][1], a[mt][2], a[mt][3],
                      za + (uint32_t)mt * (16u * ZSTRIDE * 2u) + (uint32_t)ks * 32u);
            uint32_t bf[4][4];
            #pragma unroll
            for (int np = 0; np < 4; np++)
                LDSM4(bf[np][0], bf[np][1], bf[np][2], bf[np][3],
                      bbuf + (uint32_t)np * (16u * BSTRIDE * 2u) + (uint32_t)ks * 32u);
            #pragma unroll
            for (int np = 0; np < 4; np++) {
                #pragma unroll
                for (int mt = 0; mt < 4; mt++)
                    MMA16816(acc[mt][2 * np], a[mt][0], a[mt][1], a[mt][2], a[mt][3],
                             bf[np][0], bf[np][2]);
                #pragma unroll
                for (int mt = 0; mt < 4; mt++)
                    MMA16816(acc[mt][2 * np + 1], a[mt][0], a[mt][1], a[mt][2], a[mt][3],
                             bf[np][1], bf[np][3]);
            }
        }

        if (c == NCHUNK - 1) {
            const int code0 = kbeg + ct * CTILE + wn * 64 + (lane & 3) * 2;
            #pragma unroll
            for (int nt = 0; nt < 8; nt++) {
                const int kk = code0 + nt * 8;
                const float2 cn = __ldg(reinterpret_cast<const float2*>(g_cnorm + kk));
                #pragma unroll
                for (int mt = 0; mt < 4; mt++) {
                    const int s0 = mt * 2;
                    float d0 = fmaf(-2.0f, acc[mt][nt][0], cn.x);
                    float d1 = fmaf(-2.0f, acc[mt][nt][1], cn.y);
                    if (d0 < minv[s0]) { minv[s0] = d0; mini[s0] = kk; }
                    if (d1 < minv[s0]) { minv[s0] = d1; mini[s0] = kk + 1; }
                    float d2 = fmaf(-2.0f, acc[mt][nt][2], cn.x);
                    float d3 = fmaf(-2.0f, acc[mt][nt][3], cn.y);
                    if (d2 < minv[s0 + 1]) { minv[s0 + 1] = d2; mini[s0 + 1] = kk; }
                    if (d3 < minv[s0 + 1]) { minv[s0 + 1] = d3; mini[s0 + 1] = kk + 1; }
                }
            }
        }
    }

    // ---- per-item reduce -> partials
    __syncthreads();
    float* rv = (float*)smem;
    int*   ri = (int*)smem + 512;
    #pragma unroll
    for (int s2 = 0; s2 < 8; s2++) {
        float v = minv[s2];
        int   i = mini[s2];
        #pragma unroll
        for (int off = 1; off <= 2; off <<= 1) {
            float ov = __shfl_xor_sync(0xffffffffu, v, off);
            int   oi = __shfl_xor_sync(0xffffffffu, i, off);
            if (ov < v || (ov == v && oi < i)) { v = ov; i = oi; }
        }
        if ((lane & 3) == 0) {
            int row = wm * 64 + (s2 >> 1) * 16 + (s2 & 1) * 8 + (lane >> 2);
            rv[row * 4 + wn] = v;
            ri[row * 4 + wn] = i;
        }
    }
    __syncthreads();
    if (tid < MTILE) {
        float bv = rv[tid * 4];
        int   bi = ri[tid * 4];
        #pragma unroll
        for (int t = 1; t < 4; t++) {
            float v = rv[tid * 4 + t];
            int  ii = ri[tid * 4 + t];
            if (v < bv || (v == bv && ii < bi)) { bv = v; bi = ii; }
        }
        g_pv[ksplit * NPTS + pbase + tid] = bv;
        g_pi[ksplit * NPTS + pbase + tid] = bi;
    }
}

// ---------------------------------------------------------------- reduce + accumulate
// grid = NPTS, block = 128: reduce 8 partials, write idx outputs, atomics for EMA.
__global__ void accum_reduce_kernel(const float* __restrict__ z, float* __restrict__ out) {
    __shared__ float sv[NSPLIT];
    __shared__ int   si[NSPLIT];
    const int n = blockIdx.x, d = threadIdx.x;
    if (d < NSPLIT) { sv[d] = g_pv[d * NPTS + n]; si[d] = g_pi[d * NPTS + n]; }
    __syncthreads();
    float bv = sv[0];
    int   bi = si[0];
    #pragma unroll
    for (int s = 1; s < NSPLIT; s++) {
        float v = sv[s]; int ii = si[s];
        if (v < bv || (v == bv && ii < bi)) { bv = v; bi = ii; }
    }
    const int b = n >> 10, hw = n & (HWSZ - 1);
    float zv = z[((size_t)b * DDIM + d) * HWSZ + hw];
    atomicAdd(&g_dw[bi * DDIM + d], zv);
    if (d == 0) {
        atomicAdd(&g_counts[bi], 1.0f);
        g_idx[n] = bi;
        out[O_IDX + n] = (float)bi;
    }
}

// ---------------------------------------------------------------- finalize
__global__ void finalize_kernel(const float* __restrict__ ema_count,
                                const float* __restrict__ ema_weight,
                                float* __restrict__ out) {
    int k = blockIdx.x, d = threadIdx.x;
    float cnt = ema_count[k] * 0.99f + 0.01f * g_counts[k];
    float w = ema_weight[(size_t)k * DDIM + d] * 0.99f + 0.01f * g_dw[(size_t)k * DDIM + d];
    out[O_WT + (size_t)k * DDIM + d] = w;
    out[O_CB + (size_t)k * DDIM + d] = w / fmaxf(cnt, 1.0f);
    if (d == 0) out[O_CNT + k] = cnt;
}

// ---------------------------------------------------------------- z_q output
__global__ void zq_kernel(const float* __restrict__ z,
                          const float* __restrict__ cb,
                          float* __restrict__ out) {
    __shared__ float q[32 * 129];
    const int n0 = blockIdx.x * 32;
    const int b = n0 >> 10, hw0 = n0 & (HWSZ - 1);
    for (int j = threadIdx.x; j < 32 * 128; j += 256) {
        int p = j >> 7, d = j & 127;
        q[p * 129 + d] = cb[(size_t)g_idx[n0 + p] * DDIM + d];
    }
    __syncthreads();
    const float* zp = z + (size_t)b * DDIM * HWSZ + hw0;
    float* op = out + O_ZQ + (size_t)b * DDIM * HWSZ + hw0;
    for (int j = threadIdx.x; j < 32 * 128; j += 256) {
        int d = j >> 5, p = j & 31;
        float ze = zp[(size_t)d * HWSZ + p];
        float zq = q[p * 129 + d];
        op[(size_t)d * HWSZ + p] = ze + (zq - ze);
    }
}

// ---------------------------------------------------------------- launch
extern "C" void kernel_launch(void* const* d_in, const int* in_sizes, int n_in,
                              void* d_out, int out_size) {
    const float* z_e        = (const float*)d_in[0];
    const float* codebook   = (const float*)d_in[1];
    const float* ema_count  = (const float*)d_in[2];
    const float* ema_weight = (const float*)d_in[3];
    float* out = (float*)d_out;

    const int SMEM_DYN = MTILE * ZSTRIDE * 2 + NBUF * BUFB;  // 210944
    static int smem_set = 0;
    if (!smem_set) {
        cudaFuncSetAttribute(argmin_kernel, cudaFuncAttributeMaxDynamicSharedMemorySize, SMEM_DYN);
        smem_set = 1;
    }

    prep_cb_kernel<<<KCODES, 128>>>(codebook);
    prep_z_kernel<<<NPTS / MTILE, 256>>>(z_e);
    argmin_kernel<<<NITEMS, 256, SMEM_DYN>>>();
    accum_reduce_kernel<<<NPTS, 128>>>(z_e, out);
    finalize_kernel<<<KCODES, 128>>>(ema_count, ema_weight, out);
    zq_kernel<<<NPTS / 32, 256>>>(z_e, codebook, out);
}

// round 6
// speedup vs baseline: 1.2251x; 1.1335x over previous
#include <cuda_runtime.h>
#include <cuda_fp16.h>
#include <cstdint>

// ---------------------------------------------------------------- constants
#define NPTS    16384
#define KCODES  8192
#define DDIM    128
#define HWSZ    1024
#define MTILE   128                 // points per item
#define CTILE   256                 // codes per code-tile
#define NSPLIT  8                   // K-splits (1024 codes each)
#define KPER    (KCODES / NSPLIT)
#define NCT     (KPER / CTILE)      // 4
#define NCHUNK  2                   // 64-half k-chunks (K = 128 halves, 1-term)
#define NSTAGES (NCT * NCHUNK)      // 8
#define NITEMS  (NSPLIT * (NPTS / MTILE))  // 1024
#define ZSTRIDE 136                 // halves per zs row (128 + 8 pad)
#define BSTRIDE 72                  // halves per B row (64 + 8 pad)
#define BUFB    (CTILE * BSTRIDE * 2)     // 36864 B
#define NBUF    3

// Output layout (concatenated float32 outputs)
#define O_ZQ  0
#define O_IDX 2097152
#define O_CB  2113536
#define O_CNT 3162112
#define O_WT  3170304

// ---------------------------------------------------------------- scratch
__device__ float  g_cnorm[KCODES];
__device__ float  g_cmax2;                          // max ||c||^2 (atomicMax bits)
__device__ __half g_bext[2u * KCODES * 64];         // [chunk(hi0,hi1)][code][64]
__device__ __half g_zext[NPTS * DDIM];              // fp16(z), [tile][p][128]
__device__ float  g_zf[NPTS * DDIM];                // fp32 z transposed [n][d]
__device__ float  g_znorm[NPTS];
__device__ short  g_q[(size_t)NPTS * KCODES];       // s16 approx dist*32 (permuted cols)
__device__ int    g_idx[NPTS];
__device__ float  g_counts[KCODES];
__device__ float  g_dw[KCODES * DDIM];

// ---------------------------------------------------------------- helpers
__device__ __forceinline__ uint32_t smem_u32(const void* p) {
    uint32_t a;
    asm("{ .reg .u64 t; cvta.to.shared.u64 t, %1; cvt.u32.u64 %0, t; }" : "=r"(a) : "l"(p));
    return a;
}
__device__ __forceinline__ void cp_async16(uint32_t dst, const void* src) {
    asm volatile("cp.async.cg.shared.global [%0], [%1], 16;" :: "r"(dst), "l"(src) : "memory");
}
#define CP_COMMIT() asm volatile("cp.async.commit_group;" ::: "memory")
#define CP_WAIT1()  asm volatile("cp.async.wait_group 1;" ::: "memory")
#define CP_WAIT0()  asm volatile("cp.async.wait_group 0;" ::: "memory")

#define LDSM4(r0, r1, r2, r3, a)                                              \
    asm volatile("ldmatrix.sync.aligned.m8n8.x4.shared.b16 {%0,%1,%2,%3}, [%4];" \
                 : "=r"(r0), "=r"(r1), "=r"(r2), "=r"(r3) : "r"(a))

#define MMA16816(c, a0, a1, a2, a3, b0, b1)                                  \
    asm volatile("mma.sync.aligned.m16n8k16.row.col.f32.f16.f16.f32 "        \
                 "{%0,%1,%2,%3}, {%4,%5,%6,%7}, {%8,%9}, {%0,%1,%2,%3};"     \
                 : "+f"((c)[0]), "+f"((c)[1]), "+f"((c)[2]), "+f"((c)[3])    \
                 : "r"(a0), "r"(a1), "r"(a2), "r"(a3), "r"(b0), "r"(b1))

// ---------------------------------------------------------------- init
__global__ void zero_kernel() { g_cmax2 = 0.0f; }

// ---------------------------------------------------------------- prep: codebook
// cnorm + cmax + fp16 hi split + zero accumulators. grid=K, block=128
__global__ void prep_cb_kernel(const float* __restrict__ cb) {
    int k = blockIdx.x, t = threadIdx.x;
    float v = cb[k * DDIM + t];
    g_dw[k * DDIM + t] = 0.0f;

    int half_ = t >> 6, pos = t & 63;
    g_bext[(size_t)half_ * (KCODES * 64) + (size_t)k * 64 + pos] = __float2half_rn(v);

    float sq = v * v;
    #pragma unroll
    for (int o = 16; o > 0; o >>= 1) sq += __shfl_down_sync(0xffffffffu, sq, o);
    __shared__ float red[4];
    if ((t & 31) == 0) red[t >> 5] = sq;
    __syncthreads();
    if (t == 0) {
        float cn = red[0] + red[1] + red[2] + red[3];
        g_cnorm[k] = cn;
        g_counts[k] = 0.0f;
        atomicMax((int*)&g_cmax2, __float_as_int(cn));  // cn > 0 -> int order ok
    }
}

// ---------------------------------------------------------------- prep: z side
// fp16(z) rows, fp32 transposed z, and ||z||. grid=128 tiles, block=256
__global__ void prep_z_kernel(const float* __restrict__ z) {
    __shared__ float zsm[MTILE * 129];
    const int tile = blockIdx.x, tid = threadIdx.x;
    const int pbase = tile * MTILE;
    const int b = pbase >> 10, hw0 = pbase & (HWSZ - 1);
    const float* zb = z + (size_t)b * DDIM * HWSZ + hw0;
    for (int i = tid; i < DDIM * MTILE; i += 256) {
        int d = i >> 7, p = i & 127;
        zsm[p * 129 + d] = zb[(size_t)d * HWSZ + p];
    }
    __syncthreads();
    // fp16 rows + fp32 transposed
    uint32_t* oh = reinterpret_cast<uint32_t*>(g_zext + (size_t)tile * MTILE * DDIM);
    for (int i = tid; i < MTILE * 64; i += 256) {
        int p = i >> 6, c = i & 63;
        __half2 hh = __halves2half2(__float2half_rn(zsm[p * 129 + 2 * c]),
                                    __float2half_rn(zsm[p * 129 + 2 * c + 1]));
        oh[p * 64 + c] = *reinterpret_cast<uint32_t*>(&hh);
    }
    for (int i = tid; i < MTILE * DDIM; i += 256) {
        int p = i >> 7, d = i & 127;
        g_zf[(size_t)(pbase + p) * DDIM + d] = zsm[p * 129 + d];
    }
    if (tid < MTILE) {
        float s = 0.0f;
        #pragma unroll 8
        for (int d = 0; d < DDIM; d++) { float v = zsm[tid * 129 + d]; s += v * v; }
        g_znorm[pbase + tid] = sqrtf(s);
    }
}

// ---------------------------------------------------------------- pass1: approx dist GEMM
// grid = 1024 items, block = 256 (8 warps: 2M x 4N), warp tile 64x64, K=128 fp16.
__global__ void __launch_bounds__(256, 1) dist_kernel() {
    extern __shared__ char smem[];
    char* bbase = smem + MTILE * ZSTRIDE * 2;

    const int tid = threadIdx.x;
    const int lane = tid & 31, wid = tid >> 5;
    const int wm = wid & 1;
    const int wn = wid >> 1;

    const int item = blockIdx.x;
    const int ksplit = item >> 7;
    const int tile = item & 127;
    const int kbeg = ksplit * KPER;
    const int pbase = tile * MTILE;

    const uint32_t zs32 = smem_u32(smem);
    const uint32_t bb32 = smem_u32(bbase);

    // z tile: 128 rows x 256B -> padded rows (272B), via cp.async (group 0)
    {
        const char* zsrc = (const char*)(g_zext + (size_t)tile * MTILE * DDIM);
        for (int j = tid; j < 2048; j += 256) {
            int row = j >> 4, c16 = j & 15;
            cp_async16(zs32 + (uint32_t)row * 272u + (uint32_t)c16 * 16u,
                       zsrc + (size_t)row * 256 + (size_t)c16 * 16);
        }
        CP_COMMIT();
    }

    const uint32_t za0 = zs32 + 2u * ((wm * 64 + (lane & 15)) * ZSTRIDE + (lane >> 4) * 8);
    const uint32_t bb0 = 2u * ((wn * 64 + (lane & 15)) * BSTRIDE + (lane >> 4) * 8);

    auto issue = [&](int s) {
        int ct = s >> 1, c = s & 1;
        const char* src = (const char*)(g_bext +
            ((size_t)c * KCODES + (size_t)(kbeg + ct * CTILE)) * 64);
        uint32_t dst = bb32 + (uint32_t)(s % NBUF) * BUFB;
        #pragma unroll
        for (int i = 0; i < 8; i++) {
            int idx = tid + i * 256;
            cp_async16(dst + (uint32_t)(idx >> 3) * 144u + (uint32_t)(idx & 7) * 16u,
                       src + (size_t)idx * 16);
        }
        CP_COMMIT();
    };

    float acc[4][8][4];
    issue(0);
    issue(1);

    for (int s = 0; s < NSTAGES; s++) {
        const int ct = s >> 1, c = s & 1;
        if (s + 1 < NSTAGES) CP_WAIT1(); else CP_WAIT0();
        __syncthreads();
        if (s + 2 < NSTAGES) issue(s + 2);

        if (c == 0) {
            #pragma unroll
            for (int mt = 0; mt < 4; mt++)
                #pragma unroll
                for (int nt = 0; nt < 8; nt++)
                    #pragma unroll
                    for (int r = 0; r < 4; r++) acc[mt][nt][r] = 0.0f;
        }

        const uint32_t za = za0 + (uint32_t)c * 128u;   // chunk c -> d offset c*64 halves
        const uint32_t bbuf = bb32 + (uint32_t)(s % NBUF) * BUFB + bb0;

        #pragma unroll
        for (int ks = 0; ks < 4; ks++) {
            uint32_t a[4][4];
            #pragma unroll
            for (int mt = 0; mt < 4; mt++)
                LDSM4(a[mt][0], a[mt][1], a[mt][2], a[mt][3],
                      za + (uint32_t)mt * (16u * ZSTRIDE * 2u) + (uint32_t)ks * 32u);
            uint32_t bf[4][4];
            #pragma unroll
            for (int np = 0; np < 4; np++)
                LDSM4(bf[np][0], bf[np][1], bf[np][2], bf[np][3],
                      bbuf + (uint32_t)np * (16u * BSTRIDE * 2u) + (uint32_t)ks * 32u);
            #pragma unroll
            for (int np = 0; np < 4; np++) {
                #pragma unroll
                for (int mt = 0; mt < 4; mt++)
                    MMA16816(acc[mt][2 * np], a[mt][0], a[mt][1], a[mt][2], a[mt][3],
                             bf[np][0], bf[np][2]);
                #pragma unroll
                for (int mt = 0; mt < 4; mt++)
                    MMA16816(acc[mt][2 * np + 1], a[mt][0], a[mt][1], a[mt][2], a[mt][3],
                             bf[np][1], bf[np][3]);
            }
        }

        if (c == 1) {
            // quantize (cnorm - 2*dot)*32 -> s16, packed stores (permuted col layout)
            const int kk0 = kbeg + ct * CTILE + wn * 64 + (lane & 3) * 2;
            float2 cn[8];
            #pragma unroll
            for (int nt = 0; nt < 8; nt++)
                cn[nt] = __ldg(reinterpret_cast<const float2*>(g_cnorm + kk0 + nt * 8));
            const int pcol = kbeg + ct * CTILE + wn * 64 + (lane & 3) * 16;
            #pragma unroll
            for (int mt = 0; mt < 4; mt++) {
                #pragma unroll
                for (int hf = 0; hf < 2; hf++) {
                    const int row = pbase + wm * 64 + mt * 16 + (lane >> 2) + hf * 8;
                    uint32_t r[8];
                    #pragma unroll
                    for (int nt = 0; nt < 8; nt++) {
                        float a0 = acc[mt][nt][hf * 2 + 0];
                        float a1 = acc[mt][nt][hf * 2 + 1];
                        int q0 = __float2int_rn((cn[nt].x - 2.0f * a0) * 32.0f);
                        int q1 = __float2int_rn((cn[nt].y - 2.0f * a1) * 32.0f);
                        r[nt] = (uint32_t)(q0 & 0xffff) | ((uint32_t)q1 << 16);
                    }
                    int4* gp = reinterpret_cast<int4*>(g_q + (size_t)row * KCODES + pcol);
                    gp[0] = make_int4((int)r[0], (int)r[1], (int)r[2], (int)r[3]);
                    gp[1] = make_int4((int)r[4], (int)r[5], (int)r[6], (int)r[7]);
                }
            }
        }
    }
}

// ---------------------------------------------------------------- scan + exact repair + EMA accum
// grid = NPTS blocks, block = 128. Reads the s16 row, finds candidates within a
// rigorous error bound, verifies them in exact fp32, fuses the EMA atomics.
__global__ void __launch_bounds__(128) scan_kernel(const float* __restrict__ cb,
                                                   float* __restrict__ out) {
    __shared__ float zrow[DDIM];
    __shared__ int   candk[128];
    __shared__ float cdist[128];
    __shared__ int   wmin[4];
    __shared__ int   ccnt, covf, bidx_s;

    const int n = blockIdx.x, t = threadIdx.x;
    const int lane = t & 31, w = t >> 5;

    zrow[t] = g_zf[(size_t)n * DDIM + t];
    if (t == 0) { ccnt = 0; covf = 0; }
    __syncthreads();

    const int4* qrow = reinterpret_cast<const int4*>(g_q + (size_t)n * KCODES);
    int4 v[8];
    int mn = 0x7fffffff;
    #pragma unroll
    for (int i = 0; i < 8; i++) {
        v[i] = qrow[t + i * 128];
        const uint32_t u0 = (uint32_t)v[i].x, u1 = (uint32_t)v[i].y;
        const uint32_t u2 = (uint32_t)v[i].z, u3 = (uint32_t)v[i].w;
        mn = min(mn, min((int)(short)u0, ((int)u0) >> 16));
        mn = min(mn, min((int)(short)u1, ((int)u1) >> 16));
        mn = min(mn, min((int)(short)u2, ((int)u2) >> 16));
        mn = min(mn, min((int)(short)u3, ((int)u3) >> 16));
    }
    #pragma unroll
    for (int off = 16; off > 0; off >>= 1) mn = min(mn, __shfl_xor_sync(0xffffffffu, mn, off));
    if (lane == 0) wmin[w] = mn;
    __syncthreads();
    const int mnAll = min(min(wmin[0], wmin[1]), min(wmin[2], wmin[3]));

    // rigorous threshold: |dist_err| <= 2*(2.01*2^-11*||z||*||c||max) + slop; s16 rounding +2cnt
    const float zn = g_znorm[n];
    const float cmax = sqrtf(g_cmax2);
    const float ddm = 2.0f * (2.01f * zn * cmax * (1.0f / 2048.0f)) + 0.004f;
    const int T = mnAll + (int)(64.0f * ddm) + 16;

    // collect candidates (position -> true code index via inverse permutation)
    #pragma unroll
    for (int i = 0; i < 8; i++) {
        const int pb = (t + i * 128) * 8;
        const uint32_t uu[4] = { (uint32_t)v[i].x, (uint32_t)v[i].y,
                                 (uint32_t)v[i].z, (uint32_t)v[i].w };
        #pragma unroll
        for (int j = 0; j < 4; j++) {
            int lo = (int)(short)uu[j];
            int hi = ((int)uu[j]) >> 16;
            if (lo <= T) {
                int pos = pb + j * 2;
                int k = (pos & ~63) | (((pos >> 1) & 7) << 3) | (((pos >> 4) & 3) << 1) | (pos & 1);
                int slot = atomicAdd(&ccnt, 1);
                if (slot < 128) candk[slot] = k; else covf = 1;
            }
            if (hi <= T) {
                int pos = pb + j * 2 + 1;
                int k = (pos & ~63) | (((pos >> 1) & 7) << 3) | (((pos >> 4) & 3) << 1) | (pos & 1);
                int slot = atomicAdd(&ccnt, 1);
                if (slot < 128) candk[slot] = k; else covf = 1;
            }
        }
    }
    __syncthreads();

    if (!covf) {
        const int cnt = min(ccnt, 128);
        const float4* z4p = reinterpret_cast<const float4*>(zrow);
        for (int s = w; s < cnt; s += 4) {
            const int k = candk[s];
            const float4 c4 = __ldg(reinterpret_cast<const float4*>(cb + (size_t)k * DDIM) + lane);
            const float4 z4 = z4p[lane];
            float d = c4.x * z4.x + c4.y * z4.y + c4.z * z4.z + c4.w * z4.w;
            #pragma unroll
            for (int off = 16; off > 0; off >>= 1) d += __shfl_xor_sync(0xffffffffu, d, off);
            if (lane == 0) cdist[s] = __ldg(g_cnorm + k) - 2.0f * d;
        }
        __syncthreads();
        if (t == 0) {
            float bv = cdist[0]; int bi = candk[0];
            for (int s = 1; s < cnt; s++) {
                float dv = cdist[s]; int kv = candk[s];
                if (dv < bv || (dv == bv && kv < bi)) { bv = dv; bi = kv; }
            }
            bidx_s = bi;
        }
    } else {
        // fallback: full exact scan (statistically unreachable)
        float bv = 3.402823466e38f; int bi = 0x7fffffff;
        for (int k = t; k < KCODES; k += 128) {
            float d = 0.0f;
            #pragma unroll 8
            for (int dd = 0; dd < DDIM; dd++) d += zrow[dd] * __ldg(cb + (size_t)k * DDIM + dd);
            float dist = __ldg(g_cnorm + k) - 2.0f * d;
            if (dist < bv || (dist == bv && k < bi)) { bv = dist; bi = k; }
        }
        #pragma unroll
        for (int off = 16; off > 0; off >>= 1) {
            float ov = __shfl_xor_sync(0xffffffffu, bv, off);
            int   oi = __shfl_xor_sync(0xffffffffu, bi, off);
            if (ov < bv || (ov == bv && oi < bi)) { bv = ov; bi = oi; }
        }
        if (lane == 0) { cdist[w] = bv; candk[w] = bi; }
        __syncthreads();
        if (t == 0) {
            float fv = cdist[0]; int fi = candk[0];
            for (int s = 1; s < 4; s++)
                if (cdist[s] < fv || (cdist[s] == fv && candk[s] < fi)) { fv = cdist[s]; fi = candk[s]; }
            bidx_s = fi;
        }
    }
    __syncthreads();

    const int bi = bidx_s;
    atomicAdd(&g_dw[(size_t)bi * DDIM + t], zrow[t]);
    if (t == 0) {
        atomicAdd(&g_counts[bi], 1.0f);
        g_idx[n] = bi;
        out[O_IDX + n] = (float)bi;
    }
}

// ---------------------------------------------------------------- finalize
__global__ void finalize_kernel(const float* __restrict__ ema_count,
                                const float* __restrict__ ema_weight,
                                float* __restrict__ out) {
    int k = blockIdx.x, d = threadIdx.x;
    float cnt = ema_count[k] * 0.99f + 0.01f * g_counts[k];
    float w = ema_weight[(size_t)k * DDIM + d] * 0.99f + 0.01f * g_dw[(size_t)k * DDIM + d];
    out[O_WT + (size_t)k * DDIM + d] = w;
    out[O_CB + (size_t)k * DDIM + d] = w / fmaxf(cnt, 1.0f);
    if (d == 0) out[O_CNT + k] = cnt;
}

// ---------------------------------------------------------------- z_q output
__global__ void zq_kernel(const float* __restrict__ z,
                          const float* __restrict__ cb,
                          float* __restrict__ out) {
    __shared__ float q[32 * 129];
    const int n0 = blockIdx.x * 32;
    const int b = n0 >> 10, hw0 = n0 & (HWSZ - 1);
    for (int j = threadIdx.x; j < 32 * 128; j += 256) {
        int p = j >> 7, d = j & 127;
        q[p * 129 + d] = cb[(size_t)g_idx[n0 + p] * DDIM + d];
    }
    __syncthreads();
    const float* zp = z + (size_t)b * DDIM * HWSZ + hw0;
    float* op = out + O_ZQ + (size_t)b * DDIM * HWSZ + hw0;
    for (int j = threadIdx.x; j < 32 * 128; j += 256) {
        int d = j >> 5, p = j & 31;
        float ze = zp[(size_t)d * HWSZ + p];
        float zq = q[p * 129 + d];
        op[(size_t)d * HWSZ + p] = ze + (zq - ze);
    }
}

// ---------------------------------------------------------------- launch
extern "C" void kernel_launch(void* const* d_in, const int* in_sizes, int n_in,
                              void* d_out, int out_size) {
    const float* z_e        = (const float*)d_in[0];
    const float* codebook   = (const float*)d_in[1];
    const float* ema_count  = (const float*)d_in[2];
    const float* ema_weight = (const float*)d_in[3];
    float* out = (float*)d_out;

    const int SMEM_DYN = MTILE * ZSTRIDE * 2 + NBUF * BUFB;  // 34816 + 110592 = 145408
    static int smem_set = 0;
    if (!smem_set) {
        cudaFuncSetAttribute(dist_kernel, cudaFuncAttributeMaxDynamicSharedMemorySize, SMEM_DYN);
        smem_set = 1;
    }

    zero_kernel<<<1, 1>>>();
    prep_cb_kernel<<<KCODES, 128>>>(codebook);
    prep_z_kernel<<<NPTS / MTILE, 256>>>(z_e);
    dist_kernel<<<NITEMS, 256, SMEM_DYN>>>();
    scan_kernel<<<NPTS, 128>>>(codebook, out);
    finalize_kernel<<<KCODES, 128>>>(ema_count, ema_weight, out);
    zq_kernel<<<NPTS / 32, 256>>>(z_e, codebook, out);
}

// round 8
// speedup vs baseline: 1.4080x; 1.1493x over previous
#include <cuda_runtime.h>
#include <cuda_fp16.h>
#include <cstdint>

// ---------------------------------------------------------------- constants
#define NPTS    16384
#define KCODES  8192
#define DDIM    128
#define HWSZ    1024
#define MTILE   128                 // points per item
#define CTILE   128                 // codes per code-tile (per stage)
#define NSPLIT  16                  // K-splits (512 codes each)
#define KPER    (KCODES / NSPLIT)   // 512
#define NCT     (KPER / CTILE)      // 4
#define NSTAGES (NCT * 2)           // 8 (2 k-chunks per code-tile)
#define NITEMS  (NSPLIT * (NPTS / MTILE))  // 2048
#define ZSTRIDE 136                 // halves per zs row (128 + 8 pad)
#define BSTRIDE 72                  // halves per B row (64 + 8 pad)
#define BUFB    (CTILE * BSTRIDE * 2)     // 18432 B
#define NBUF    3

// Output layout (concatenated float32 outputs)
#define O_ZQ  0
#define O_IDX 2097152
#define O_CB  2113536
#define O_CNT 3162112
#define O_WT  3170304

// ---------------------------------------------------------------- scratch
__device__ float  g_cnorm[KCODES];
__device__ float  g_cmax2;                          // max ||c||^2
__device__ __half g_bext[2u * KCODES * 64];         // [chunk(hi0,hi1)][code][64]
__device__ __half g_zext[NPTS * DDIM];              // fp16(z) rows
__device__ float  g_zf[NPTS * DDIM];                // fp32 z rows
__device__ float  g_znorm[NPTS];
__device__ short  g_q[(size_t)NPTS * KCODES];       // s16 approx dist*32 (permuted cols)
__device__ int    g_idx[NPTS];
__device__ float  g_counts[KCODES];
__device__ float  g_dw[KCODES * DDIM];

// ---------------------------------------------------------------- helpers
__device__ __forceinline__ uint32_t smem_u32(const void* p) {
    uint32_t a;
    asm("{ .reg .u64 t; cvta.to.shared.u64 t, %1; cvt.u32.u64 %0, t; }" : "=r"(a) : "l"(p));
    return a;
}
__device__ __forceinline__ void cp_async16(uint32_t dst, const void* src) {
    asm volatile("cp.async.cg.shared.global [%0], [%1], 16;" :: "r"(dst), "l"(src) : "memory");
}
#define CP_COMMIT() asm volatile("cp.async.commit_group;" ::: "memory")
#define CP_WAIT1()  asm volatile("cp.async.wait_group 1;" ::: "memory")
#define CP_WAIT0()  asm volatile("cp.async.wait_group 0;" ::: "memory")

#define LDSM4(r0, r1, r2, r3, a)                                              \
    asm volatile("ldmatrix.sync.aligned.m8n8.x4.shared.b16 {%0,%1,%2,%3}, [%4];" \
                 : "=r"(r0), "=r"(r1), "=r"(r2), "=r"(r3) : "r"(a))

#define MMA16816(c, a0, a1, a2, a3, b0, b1)                                  \
    asm volatile("mma.sync.aligned.m16n8k16.row.col.f32.f16.f16.f32 "        \
                 "{%0,%1,%2,%3}, {%4,%5,%6,%7}, {%8,%9}, {%0,%1,%2,%3};"     \
                 : "+f"((c)[0]), "+f"((c)[1]), "+f"((c)[2]), "+f"((c)[3])    \
                 : "r"(a0), "r"(a1), "r"(a2), "r"(a3), "r"(b0), "r"(b1))

// ---------------------------------------------------------------- init
__global__ void zero_kernel() { g_cmax2 = 0.0f; }

// ---------------------------------------------------------------- prep: codebook
__global__ void prep_cb_kernel(const float* __restrict__ cb) {
    int k = blockIdx.x, t = threadIdx.x;
    float v = cb[k * DDIM + t];
    g_dw[k * DDIM + t] = 0.0f;

    int half_ = t >> 6, pos = t & 63;
    g_bext[(size_t)half_ * (KCODES * 64) + (size_t)k * 64 + pos] = __float2half_rn(v);

    float sq = v * v;
    #pragma unroll
    for (int o = 16; o > 0; o >>= 1) sq += __shfl_down_sync(0xffffffffu, sq, o);
    __shared__ float red[4];
    if ((t & 31) == 0) red[t >> 5] = sq;
    __syncthreads();
    if (t == 0) {
        float cn = red[0] + red[1] + red[2] + red[3];
        g_cnorm[k] = cn;
        g_counts[k] = 0.0f;
        atomicMax((int*)&g_cmax2, __float_as_int(cn));  // cn > 0 -> int order ok
    }
}

// ---------------------------------------------------------------- prep: z side
__global__ void prep_z_kernel(const float* __restrict__ z) {
    __shared__ float zsm[MTILE * 129];
    const int tile = blockIdx.x, tid = threadIdx.x;
    const int pbase = tile * MTILE;
    const int b = pbase >> 10, hw0 = pbase & (HWSZ - 1);
    const float* zb = z + (size_t)b * DDIM * HWSZ + hw0;
    for (int i = tid; i < DDIM * MTILE; i += 256) {
        int d = i >> 7, p = i & 127;
        zsm[p * 129 + d] = zb[(size_t)d * HWSZ + p];
    }
    __syncthreads();
    uint32_t* oh = reinterpret_cast<uint32_t*>(g_zext + (size_t)tile * MTILE * DDIM);
    for (int i = tid; i < MTILE * 64; i += 256) {
        int p = i >> 6, c = i & 63;
        __half2 hh = __halves2half2(__float2half_rn(zsm[p * 129 + 2 * c]),
                                    __float2half_rn(zsm[p * 129 + 2 * c + 1]));
        oh[p * 64 + c] = *reinterpret_cast<uint32_t*>(&hh);
    }
    for (int i = tid; i < MTILE * DDIM; i += 256) {
        int p = i >> 7, d = i & 127;
        g_zf[(size_t)(pbase + p) * DDIM + d] = zsm[p * 129 + d];
    }
    if (tid < MTILE) {
        float s = 0.0f;
        #pragma unroll 8
        for (int d = 0; d < DDIM; d++) { float v = zsm[tid * 129 + d]; s += v * v; }
        g_znorm[pbase + tid] = sqrtf(s);
    }
}

// ---------------------------------------------------------------- pass1: approx dist GEMM (s16)
// grid = 2048 items, block = 256 (8 warps: 4M x 2N), warp tile 32x64, 2 CTAs/SM.
__global__ void __launch_bounds__(256, 2) dist_kernel() {
    extern __shared__ char smem[];
    char* bbase = smem + MTILE * ZSTRIDE * 2;

    const int tid = threadIdx.x;
    const int lane = tid & 31, wid = tid >> 5;
    const int wm = wid & 3;        // 4 M blocks of 32
    const int wn = wid >> 2;       // 2 N blocks of 64

    const int item = blockIdx.x;
    const int ksplit = item >> 7;          // 0..15
    const int tile = item & 127;
    const int kbeg = ksplit * KPER;
    const int pbase = tile * MTILE;

    const uint32_t zs32 = smem_u32(smem);
    const uint32_t bb32 = smem_u32(bbase);

    // z tile (group 0): 128 rows x 256B into padded 272B rows
    {
        const char* zsrc = (const char*)(g_zext + (size_t)tile * MTILE * DDIM);
        for (int j = tid; j < 2048; j += 256) {
            int row = j >> 4, c16 = j & 15;
            cp_async16(zs32 + (uint32_t)row * 272u + (uint32_t)c16 * 16u,
                       zsrc + (size_t)row * 256 + (size_t)c16 * 16);
        }
        CP_COMMIT();
    }

    const uint32_t za0 = zs32 + 2u * ((wm * 32 + (lane & 15)) * ZSTRIDE + (lane >> 4) * 8);
    const uint32_t bb0 = 2u * ((wn * 64 + (lane & 15)) * BSTRIDE + (lane >> 4) * 8);

    auto issue = [&](int s) {
        int ct = s >> 1, c = s & 1;
        const char* src = (const char*)(g_bext +
            ((size_t)c * KCODES + (size_t)(kbeg + ct * CTILE)) * 64);
        uint32_t dst = bb32 + (uint32_t)(s % NBUF) * BUFB;
        #pragma unroll
        for (int i = 0; i < 4; i++) {
            int idx = tid + i * 256;          // 0..1023 16B chunks (128 rows x 8)
            cp_async16(dst + (uint32_t)(idx >> 3) * 144u + (uint32_t)(idx & 7) * 16u,
                       src + (size_t)idx * 16);
        }
        CP_COMMIT();
    };

    float acc[2][8][4];
    issue(0);
    issue(1);

    for (int s = 0; s < NSTAGES; s++) {
        const int ct = s >> 1, c = s & 1;
        if (s + 1 < NSTAGES) CP_WAIT1(); else CP_WAIT0();
        __syncthreads();
        if (s + 2 < NSTAGES) issue(s + 2);

        if (c == 0) {
            #pragma unroll
            for (int mt = 0; mt < 2; mt++)
                #pragma unroll
                for (int nt = 0; nt < 8; nt++)
                    #pragma unroll
                    for (int r = 0; r < 4; r++) acc[mt][nt][r] = 0.0f;
        }

        const uint32_t za = za0 + (uint32_t)c * 128u;   // chunk offset: c*64 halves
        const uint32_t bbuf = bb32 + (uint32_t)(s % NBUF) * BUFB + bb0;

        #pragma unroll
        for (int ks = 0; ks < 4; ks++) {
            uint32_t a[2][4];
            #pragma unroll
            for (int mt = 0; mt < 2; mt++)
                LDSM4(a[mt][0], a[mt][1], a[mt][2], a[mt][3],
                      za + (uint32_t)mt * (16u * ZSTRIDE * 2u) + (uint32_t)ks * 32u);
            uint32_t bf[4][4];
            #pragma unroll
            for (int np = 0; np < 4; np++)
                LDSM4(bf[np][0], bf[np][1], bf[np][2], bf[np][3],
                      bbuf + (uint32_t)np * (16u * BSTRIDE * 2u) + (uint32_t)ks * 32u);
            #pragma unroll
            for (int np = 0; np < 4; np++) {
                #pragma unroll
                for (int mt = 0; mt < 2; mt++)
                    MMA16816(acc[mt][2 * np], a[mt][0], a[mt][1], a[mt][2], a[mt][3],
                             bf[np][0], bf[np][2]);
                #pragma unroll
                for (int mt = 0; mt < 2; mt++)
                    MMA16816(acc[mt][2 * np + 1], a[mt][0], a[mt][1], a[mt][2], a[mt][3],
                             bf[np][1], bf[np][3]);
            }
        }

        if (c == 1) {
            // quantize (cnorm - 2*dot)*32 -> s16, packed stores (same layout as R6)
            const int kk0 = kbeg + ct * CTILE + wn * 64 + (lane & 3) * 2;
            float2 cn[8];
            #pragma unroll
            for (int nt = 0; nt < 8; nt++)
                cn[nt] = __ldg(reinterpret_cast<const float2*>(g_cnorm + kk0 + nt * 8));
            const int pcol = kbeg + ct * CTILE + wn * 64 + (lane & 3) * 16;
            #pragma unroll
            for (int mt = 0; mt < 2; mt++) {
                #pragma unroll
                for (int hf = 0; hf < 2; hf++) {
                    const int row = pbase + wm * 32 + mt * 16 + (lane >> 2) + hf * 8;
                    uint32_t r[8];
                    #pragma unroll
                    for (int nt = 0; nt < 8; nt++) {
                        float a0 = acc[mt][nt][hf * 2 + 0];
                        float a1 = acc[mt][nt][hf * 2 + 1];
                        int q0 = __float2int_rn((cn[nt].x - 2.0f * a0) * 32.0f);
                        int q1 = __float2int_rn((cn[nt].y - 2.0f * a1) * 32.0f);
                        r[nt] = (uint32_t)(q0 & 0xffff) | ((uint32_t)q1 << 16);
                    }
                    int4* gp = reinterpret_cast<int4*>(g_q + (size_t)row * KCODES + pcol);
                    gp[0] = make_int4((int)r[0], (int)r[1], (int)r[2], (int)r[3]);
                    gp[1] = make_int4((int)r[4], (int)r[5], (int)r[6], (int)r[7]);
                }
            }
        }
    }
}

// ---------------------------------------------------------------- scan + exact repair + EMA accum
// (verbatim from the passing Round-6 kernel)
__global__ void __launch_bounds__(128) scan_kernel(const float* __restrict__ cb,
                                                   float* __restrict__ out) {
    __shared__ float zrow[DDIM];
    __shared__ int   candk[128];
    __shared__ float cdist[128];
    __shared__ int   wmin[4];
    __shared__ int   ccnt, covf, bidx_s;

    const int n = blockIdx.x, t = threadIdx.x;
    const int lane = t & 31, w = t >> 5;

    zrow[t] = g_zf[(size_t)n * DDIM + t];
    if (t == 0) { ccnt = 0; covf = 0; }
    __syncthreads();

    const int4* qrow = reinterpret_cast<const int4*>(g_q + (size_t)n * KCODES);
    int4 v[8];
    int mn = 0x7fffffff;
    #pragma unroll
    for (int i = 0; i < 8; i++) {
        v[i] = qrow[t + i * 128];
        const uint32_t u0 = (uint32_t)v[i].x, u1 = (uint32_t)v[i].y;
        const uint32_t u2 = (uint32_t)v[i].z, u3 = (uint32_t)v[i].w;
        mn = min(mn, min((int)(short)u0, ((int)u0) >> 16));
        mn = min(mn, min((int)(short)u1, ((int)u1) >> 16));
        mn = min(mn, min((int)(short)u2, ((int)u2) >> 16));
        mn = min(mn, min((int)(short)u3, ((int)u3) >> 16));
    }
    #pragma unroll
    for (int off = 16; off > 0; off >>= 1) mn = min(mn, __shfl_xor_sync(0xffffffffu, mn, off));
    if (lane == 0) wmin[w] = mn;
    __syncthreads();
    const int mnAll = min(min(wmin[0], wmin[1]), min(wmin[2], wmin[3]));

    const float zn = g_znorm[n];
    const float cmax = sqrtf(g_cmax2);
    const float ddm = 2.0f * (2.01f * zn * cmax * (1.0f / 2048.0f)) + 0.004f;
    const int T = mnAll + (int)(64.0f * ddm) + 16;

    #pragma unroll
    for (int i = 0; i < 8; i++) {
        const int pb = (t + i * 128) * 8;
        const uint32_t uu[4] = { (uint32_t)v[i].x, (uint32_t)v[i].y,
                                 (uint32_t)v[i].z, (uint32_t)v[i].w };
        #pragma unroll
        for (int j = 0; j < 4; j++) {
            int lo = (int)(short)uu[j];
            int hi = ((int)uu[j]) >> 16;
            if (lo <= T) {
                int pos = pb + j * 2;
                int k = (pos & ~63) | (((pos >> 1) & 7) << 3) | (((pos >> 4) & 3) << 1) | (pos & 1);
                int slot = atomicAdd(&ccnt, 1);
                if (slot < 128) candk[slot] = k; else covf = 1;
            }
            if (hi <= T) {
                int pos = pb + j * 2 + 1;
                int k = (pos & ~63) | (((pos >> 1) & 7) << 3) | (((pos >> 4) & 3) << 1) | (pos & 1);
                int slot = atomicAdd(&ccnt, 1);
                if (slot < 128) candk[slot] = k; else covf = 1;
            }
        }
    }
    __syncthreads();

    if (!covf) {
        const int cnt = min(ccnt, 128);
        const float4* z4p = reinterpret_cast<const float4*>(zrow);
        for (int s = w; s < cnt; s += 4) {
            const int k = candk[s];
            const float4 c4 = __ldg(reinterpret_cast<const float4*>(cb + (size_t)k * DDIM) + lane);
            const float4 z4 = z4p[lane];
            float d = c4.x * z4.x + c4.y * z4.y + c4.z * z4.z + c4.w * z4.w;
            #pragma unroll
            for (int off = 16; off > 0; off >>= 1) d += __shfl_xor_sync(0xffffffffu, d, off);
            if (lane == 0) cdist[s] = __ldg(g_cnorm + k) - 2.0f * d;
        }
        __syncthreads();
        if (t == 0) {
            float bv = cdist[0]; int bi = candk[0];
            for (int s = 1; s < cnt; s++) {
                float dv = cdist[s]; int kv = candk[s];
                if (dv < bv || (dv == bv && kv < bi)) { bv = dv; bi = kv; }
            }
            bidx_s = bi;
        }
    } else {
        float bv = 3.402823466e38f; int bi = 0x7fffffff;
        for (int k = t; k < KCODES; k += 128) {
            float d = 0.0f;
            #pragma unroll 8
            for (int dd = 0; dd < DDIM; dd++) d += zrow[dd] * __ldg(cb + (size_t)k * DDIM + dd);
            float dist = __ldg(g_cnorm + k) - 2.0f * d;
            if (dist < bv || (dist == bv && k < bi)) { bv = dist; bi = k; }
        }
        #pragma unroll
        for (int off = 16; off > 0; off >>= 1) {
            float ov = __shfl_xor_sync(0xffffffffu, bv, off);
            int   oi = __shfl_xor_sync(0xffffffffu, bi, off);
            if (ov < bv || (ov == bv && oi < bi)) { bv = ov; bi = oi; }
        }
        if (lane == 0) { cdist[w] = bv; candk[w] = bi; }
        __syncthreads();
        if (t == 0) {
            float fv = cdist[0]; int fi = candk[0];
            for (int s = 1; s < 4; s++)
                if (cdist[s] < fv || (cdist[s] == fv && candk[s] < fi)) { fv = cdist[s]; fi = candk[s]; }
            bidx_s = fi;
        }
    }
    __syncthreads();

    const int bi = bidx_s;
    atomicAdd(&g_dw[(size_t)bi * DDIM + t], zrow[t]);
    if (t == 0) {
        atomicAdd(&g_counts[bi], 1.0f);
        g_idx[n] = bi;
        out[O_IDX + n] = (float)bi;
    }
}

// ---------------------------------------------------------------- finalize
__global__ void finalize_kernel(const float* __restrict__ ema_count,
                                const float* __restrict__ ema_weight,
                                float* __restrict__ out) {
    int k = blockIdx.x, d = threadIdx.x;
    float cnt = ema_count[k] * 0.99f + 0.01f * g_counts[k];
    float w = ema_weight[(size_t)k * DDIM + d] * 0.99f + 0.01f * g_dw[(size_t)k * DDIM + d];
    out[O_WT + (size_t)k * DDIM + d] = w;
    out[O_CB + (size_t)k * DDIM + d] = w / fmaxf(cnt, 1.0f);
    if (d == 0) out[O_CNT + k] = cnt;
}

// ---------------------------------------------------------------- z_q output
__global__ void zq_kernel(const float* __restrict__ z,
                          const float* __restrict__ cb,
                          float* __restrict__ out) {
    __shared__ float q[32 * 129];
    const int n0 = blockIdx.x * 32;
    const int b = n0 >> 10, hw0 = n0 & (HWSZ - 1);
    for (int j = threadIdx.x; j < 32 * 128; j += 256) {
        int p = j >> 7, d = j & 127;
        q[p * 129 + d] = cb[(size_t)g_idx[n0 + p] * DDIM + d];
    }
    __syncthreads();
    const float* zp = z + (size_t)b * DDIM * HWSZ + hw0;
    float* op = out + O_ZQ + (size_t)b * DDIM * HWSZ + hw0;
    for (int j = threadIdx.x; j < 32 * 128; j += 256) {
        int d = j >> 5, p = j & 31;
        float ze = zp[(size_t)d * HWSZ + p];
        float zq = q[p * 129 + d];
        op[(size_t)d * HWSZ + p] = ze + (zq - ze);
    }
}

// ---------------------------------------------------------------- launch
extern "C" void kernel_launch(void* const* d_in, const int* in_sizes, int n_in,
                              void* d_out, int out_size) {
    const float* z_e        = (const float*)d_in[0];
    const float* codebook   = (const float*)d_in[1];
    const float* ema_count  = (const float*)d_in[2];
    const float* ema_weight = (const float*)d_in[3];
    float* out = (float*)d_out;

    const int SMEM_DYN = MTILE * ZSTRIDE * 2 + NBUF * BUFB;  // 34816 + 55296 = 90112
    static int smem_set = 0;
    if (!smem_set) {
        cudaFuncSetAttribute(dist_kernel, cudaFuncAttributeMaxDynamicSharedMemorySize, SMEM_DYN);
        smem_set = 1;
    }

    zero_kernel<<<1, 1>>>();
    prep_cb_kernel<<<KCODES, 128>>>(codebook);
    prep_z_kernel<<<NPTS / MTILE, 256>>>(z_e);
    dist_kernel<<<NITEMS, 256, SMEM_DYN>>>();
    scan_kernel<<<NPTS, 128>>>(codebook, out);
    finalize_kernel<<<KCODES, 128>>>(ema_count, ema_weight, out);
    zq_kernel<<<NPTS / 32, 256>>>(z_e, codebook, out);
}